// round 1
// baseline (speedup 1.0000x reference)
#include <cuda_runtime.h>
#include <cuda_bf16.h>
#include <stdint.h>

// Problem constants (fixed shapes)
#define MAXN 50000
#define DH   64

// Scratch (allocation-free rule: __device__ globals)
__device__ float g_dinv[MAXN];
__device__ float g_bufA[MAXN * DH];
__device__ float g_bufB[MAXN * DH];
__device__ float g_bufC[MAXN * DH];
__device__ int   g_is64;

// ---------------------------------------------------------------------------
// edge index dtype detection: if int64 (little-endian), odd 32-bit words == 0
__global__ void k_detect(const int* __restrict__ e) {
    int is64 = 1;
#pragma unroll
    for (int i = 0; i < 8; ++i)
        if (e[2 * i + 1] != 0) is64 = 0;
    g_is64 = is64;
}

__device__ __forceinline__ long long load_idx(const void* p, long long i, int is64) {
    if (is64) return ((const long long*)p)[i];
    return (long long)((const int*)p)[i];
}

// ---------------------------------------------------------------------------
__global__ void k_deg_init(float* deg, int n) {
    int i = blockIdx.x * blockDim.x + threadIdx.x;
    if (i < n) deg[i] = 1.0f;  // self-loop
}

__global__ void k_deg_acc(const void* __restrict__ edge, float* deg, int e) {
    int i = blockIdx.x * blockDim.x + threadIdx.x;
    if (i >= e) return;
    int is64 = g_is64;
    long long d = load_idx(edge, (long long)e + i, is64);  // dst row
    atomicAdd(&deg[d], 1.0f);
}

__global__ void k_dinv(float* deg, int n) {
    int i = blockIdx.x * blockDim.x + threadIdx.x;
    if (i < n) deg[i] = rsqrtf(deg[i]);
}

// ---------------------------------------------------------------------------
// Y[n,64] = X[n,K] @ W[K,64]  (+bias, +relu per MODE)
// MODE: 0 = plain, 1 = +bias, 2 = +bias+relu
template <int K, int MODE>
__global__ void k_gemm(const float* __restrict__ X, const float* __restrict__ W,
                       const float* __restrict__ b, float* __restrict__ Y, int n) {
    __shared__ float sW[K * 64];
    __shared__ float sX[4][K];
    int tid = threadIdx.x;  // 256
    for (int i = tid; i < K * 64; i += 256) sW[i] = W[i];
    int row0 = blockIdx.x * 4;
    for (int i = tid; i < 4 * K; i += 256) {
        int r = i / K, c = i - r * K;
        int row = row0 + r;
        sX[r][c] = (row < n) ? X[(long long)row * K + c] : 0.0f;
    }
    __syncthreads();
    int r = tid >> 6;
    int j = tid & 63;
    int row = row0 + r;
    if (row >= n) return;
    float acc = 0.0f;
#pragma unroll
    for (int k = 0; k < K; ++k) acc = fmaf(sX[r][k], sW[k * 64 + j], acc);
    if (MODE >= 1) acc += b[j];
    if (MODE == 2) acc = fmaxf(acc, 0.0f);
    Y[(long long)row * 64 + j] = acc;
}

// ---------------------------------------------------------------------------
__global__ void k_zero(float* p, long long n) {
    long long i = (long long)blockIdx.x * blockDim.x + threadIdx.x;
    if (i < n) p[i] = 0.0f;
}

// One warp per edge; lane handles features {lane, lane+32}
__global__ void k_scatter(const void* __restrict__ edge, const float* __restrict__ dinv,
                          const float* __restrict__ H, float* __restrict__ out, int e) {
    int gw = (blockIdx.x * blockDim.x + threadIdx.x) >> 5;
    int lane = threadIdx.x & 31;
    if (gw >= e) return;
    int is64 = g_is64;
    long long s = load_idx(edge, gw, is64);
    long long d = load_idx(edge, (long long)e + gw, is64);
    float norm = __ldg(&dinv[s]) * __ldg(&dinv[d]);
    const float* hp = H + s * 64;
    float* op = out + d * 64;
    float v0 = __ldg(&hp[lane]) * norm;
    float v1 = __ldg(&hp[lane + 32]) * norm;
    atomicAdd(&op[lane], v0);
    atomicAdd(&op[lane + 32], v1);
}

// out = [relu](agg + hw*dinv^2 + b)
template <int RELU>
__global__ void k_finalize(const float* __restrict__ agg, const float* __restrict__ hw,
                           const float* __restrict__ dinv, const float* __restrict__ b,
                           float* __restrict__ out, int n) {
    long long idx = (long long)blockIdx.x * blockDim.x + threadIdx.x;
    if (idx >= (long long)n * 64) return;
    int i = (int)(idx >> 6);
    int j = (int)(idx & 63);
    float di = dinv[i];
    float v = agg[idx] + hw[idx] * di * di + b[j];
    if (RELU) v = fmaxf(v, 0.0f);
    out[idx] = v;
}

// ---------------------------------------------------------------------------
extern "C" void kernel_launch(void* const* d_in, const int* in_sizes, int n_in,
                              void* d_out, int out_size) {
    const float* x    = (const float*)d_in[0];
    const void*  eidx = d_in[1];
    const float* W1   = (const float*)d_in[2];
    const float* b1   = (const float*)d_in[3];
    const float* W2   = (const float*)d_in[4];
    const float* b2   = (const float*)d_in[5];
    const float* Wp1  = (const float*)d_in[6];
    const float* bp1  = (const float*)d_in[7];
    const float* Wp2  = (const float*)d_in[8];
    const float* bp2  = (const float*)d_in[9];

    const int N = in_sizes[0] / 128;      // 50000
    const int E = in_sizes[1] / 2;        // 800000

    float* dinv; cudaGetSymbolAddress((void**)&dinv, g_dinv);
    float* bufA; cudaGetSymbolAddress((void**)&bufA, g_bufA);
    float* bufB; cudaGetSymbolAddress((void**)&bufB, g_bufB);
    float* bufC; cudaGetSymbolAddress((void**)&bufC, g_bufC);

    float* zout = (float*)d_out;              // z : N*64
    float* pout = zout + (long long)N * 64;   // p : N*64

    const long long NF = (long long)N * 64;
    const int TB = 256;
    const int gN   = (N + TB - 1) / TB;
    const int gE   = (E + TB - 1) / TB;
    const int gNF  = (int)((NF + TB - 1) / TB);
    const int gSc  = (E * 32 + TB - 1) / TB;  // warp per edge
    const int gGem = (N + 3) / 4;

    // dtype detection + degree
    k_detect<<<1, 1>>>((const int*)eidx);
    k_deg_init<<<gN, TB>>>(dinv, N);
    k_deg_acc<<<gE, TB>>>(eidx, dinv, E);
    k_dinv<<<gN, TB>>>(dinv, N);

    // ---- layer 1: h = relu(norm_agg(x@W1) + b1)
    k_gemm<128, 0><<<gGem, TB>>>(x, W1, nullptr, bufA, N);
    k_zero<<<gNF, TB>>>(bufB, NF);
    k_scatter<<<gSc, TB>>>(eidx, dinv, bufA, bufB, E);
    k_finalize<1><<<gNF, TB>>>(bufB, bufA, dinv, b1, bufC, N);  // h -> bufC

    // ---- layer 2: z = norm_agg(h@W2) + b2
    k_gemm<64, 0><<<gGem, TB>>>(bufC, W2, nullptr, bufA, N);
    k_zero<<<gNF, TB>>>(bufB, NF);
    k_scatter<<<gSc, TB>>>(eidx, dinv, bufA, bufB, E);
    k_finalize<0><<<gNF, TB>>>(bufB, bufA, dinv, b2, zout, N);  // z -> d_out

    // ---- head: p = relu(z@Wp1 + bp1) @ Wp2 + bp2
    k_gemm<64, 2><<<gGem, TB>>>(zout, Wp1, bp1, bufC, N);
    k_gemm<64, 1><<<gGem, TB>>>(bufC, Wp2, bp2, pout, N);
}

// round 2
// speedup vs baseline: 1.1715x; 1.1715x over previous
#include <cuda_runtime.h>
#include <cuda_bf16.h>
#include <stdint.h>

#define MAXN 50000
#define MAXE 800000
#define DH   64

// Scratch (allocation-free rule: __device__ globals)
__device__ __align__(256) float g_dinv[MAXN];
__device__ __align__(256) float g_bufA[MAXN * DH];
__device__ __align__(256) float g_bufB[MAXN * DH];
__device__ __align__(256) float g_bufC[MAXN * DH];
__device__ __align__(256) int   g_src[MAXE];
__device__ __align__(256) int   g_dst[MAXE];
__device__ __align__(256) float g_norm[MAXE];
__device__ int g_is64;

// ---------------------------------------------------------------------------
// edge index dtype detection: if int64 (little-endian), odd 32-bit words == 0
__global__ void k_detect(const int* __restrict__ e) {
    int is64 = 1;
#pragma unroll
    for (int i = 0; i < 8; ++i)
        if (e[2 * i + 1] != 0) is64 = 0;
    g_is64 = is64;
}

// Convert edge indices to int32 arrays (once; both scatter passes reuse)
__global__ void k_prep(const void* __restrict__ edge, int* __restrict__ src,
                       int* __restrict__ dst, int e) {
    int i = blockIdx.x * blockDim.x + threadIdx.x;
    if (i >= e) return;
    if (g_is64) {
        const long long* p = (const long long*)edge;
        src[i] = (int)p[i];
        dst[i] = (int)p[(long long)e + i];
    } else {
        const int* p = (const int*)edge;
        src[i] = p[i];
        dst[i] = p[e + i];
    }
}

__global__ void k_deg_init(float* deg, int n) {
    int i = blockIdx.x * blockDim.x + threadIdx.x;
    if (i < n) deg[i] = 1.0f;  // self-loop
}

__global__ void k_deg_acc(const int* __restrict__ dst, float* deg, int e) {
    int i = blockIdx.x * blockDim.x + threadIdx.x;
    if (i < e) atomicAdd(&deg[dst[i]], 1.0f);
}

__global__ void k_dinv(float* deg, int n) {
    int i = blockIdx.x * blockDim.x + threadIdx.x;
    if (i < n) deg[i] = rsqrtf(deg[i]);
}

__global__ void k_norm(const int* __restrict__ src, const int* __restrict__ dst,
                       const float* __restrict__ dinv, float* __restrict__ norm, int e) {
    int i = blockIdx.x * blockDim.x + threadIdx.x;
    if (i < e) norm[i] = __ldg(&dinv[src[i]]) * __ldg(&dinv[dst[i]]);
}

// ---------------------------------------------------------------------------
// Y[n,64] = X[n,K] @ W[K,64]  (+bias, +relu per MODE)
template <int K, int MODE>
__global__ void k_gemm(const float* __restrict__ X, const float* __restrict__ W,
                       const float* __restrict__ b, float* __restrict__ Y, int n) {
    __shared__ float sW[K * 64];
    __shared__ float sX[4][K];
    int tid = threadIdx.x;  // 256
    for (int i = tid; i < K * 64; i += 256) sW[i] = W[i];
    int row0 = blockIdx.x * 4;
    for (int i = tid; i < 4 * K; i += 256) {
        int r = i / K, c = i - r * K;
        int row = row0 + r;
        sX[r][c] = (row < n) ? X[(long long)row * K + c] : 0.0f;
    }
    __syncthreads();
    int r = tid >> 6;
    int j = tid & 63;
    int row = row0 + r;
    if (row >= n) return;
    float acc = 0.0f;
#pragma unroll
    for (int k = 0; k < K; ++k) acc = fmaf(sX[r][k], sW[k * 64 + j], acc);
    if (MODE >= 1) acc += b[j];
    if (MODE == 2) acc = fmaxf(acc, 0.0f);
    Y[(long long)row * 64 + j] = acc;
}

// ---------------------------------------------------------------------------
__global__ void k_zero4(float4* p, long long n4) {
    long long i = (long long)blockIdx.x * blockDim.x + threadIdx.x;
    if (i < n4) p[i] = make_float4(0.f, 0.f, 0.f, 0.f);
}

// Half-warp (16 lanes) per edge; each lane: one float4 gather + one v4 reduction.
__global__ void k_scatter(const int* __restrict__ src, const int* __restrict__ dst,
                          const float* __restrict__ norm, const float* __restrict__ H,
                          float* __restrict__ out, int e) {
    int gid = blockIdx.x * blockDim.x + threadIdx.x;
    int eidx = gid >> 4;
    int lane = gid & 15;
    if (eidx >= e) return;
    int s = __ldg(&src[eidx]);
    int d = __ldg(&dst[eidx]);
    float nm = __ldg(&norm[eidx]);
    float4 v = __ldg((const float4*)(H + (long long)s * 64) + lane);
    v.x *= nm; v.y *= nm; v.z *= nm; v.w *= nm;
    float* op = out + (long long)d * 64 + lane * 4;
    asm volatile("red.global.add.v4.f32 [%0], {%1, %2, %3, %4};"
                 :: "l"(op), "f"(v.x), "f"(v.y), "f"(v.z), "f"(v.w) : "memory");
}

// out = [relu](agg + hw*dinv^2 + b)   (float4 over feature dim: 16 groups/row)
template <int RELU>
__global__ void k_finalize(const float4* __restrict__ agg, const float4* __restrict__ hw,
                           const float* __restrict__ dinv, const float4* __restrict__ b,
                           float4* __restrict__ out, int n) {
    long long idx = (long long)blockIdx.x * blockDim.x + threadIdx.x;
    if (idx >= (long long)n * 16) return;
    int i = (int)(idx >> 4);
    int j = (int)(idx & 15);
    float di = dinv[i];
    float d2 = di * di;
    float4 a = agg[idx];
    float4 h = hw[idx];
    float4 bb = __ldg(&b[j]);
    float4 v;
    v.x = fmaf(h.x, d2, a.x) + bb.x;
    v.y = fmaf(h.y, d2, a.y) + bb.y;
    v.z = fmaf(h.z, d2, a.z) + bb.z;
    v.w = fmaf(h.w, d2, a.w) + bb.w;
    if (RELU) {
        v.x = fmaxf(v.x, 0.f); v.y = fmaxf(v.y, 0.f);
        v.z = fmaxf(v.z, 0.f); v.w = fmaxf(v.w, 0.f);
    }
    out[idx] = v;
}

// ---------------------------------------------------------------------------
extern "C" void kernel_launch(void* const* d_in, const int* in_sizes, int n_in,
                              void* d_out, int out_size) {
    const float* x    = (const float*)d_in[0];
    const void*  eidx = d_in[1];
    const float* W1   = (const float*)d_in[2];
    const float* b1   = (const float*)d_in[3];
    const float* W2   = (const float*)d_in[4];
    const float* b2   = (const float*)d_in[5];
    const float* Wp1  = (const float*)d_in[6];
    const float* bp1  = (const float*)d_in[7];
    const float* Wp2  = (const float*)d_in[8];
    const float* bp2  = (const float*)d_in[9];

    const int N = in_sizes[0] / 128;      // 50000
    const int E = in_sizes[1] / 2;        // 800000

    float* dinv; cudaGetSymbolAddress((void**)&dinv, g_dinv);
    float* bufA; cudaGetSymbolAddress((void**)&bufA, g_bufA);
    float* bufB; cudaGetSymbolAddress((void**)&bufB, g_bufB);
    float* bufC; cudaGetSymbolAddress((void**)&bufC, g_bufC);
    int*   srcI; cudaGetSymbolAddress((void**)&srcI, g_src);
    int*   dstI; cudaGetSymbolAddress((void**)&dstI, g_dst);
    float* nrm;  cudaGetSymbolAddress((void**)&nrm,  g_norm);

    float* zout = (float*)d_out;
    float* pout = zout + (long long)N * 64;

    const long long NF4 = (long long)N * 16;  // float4 elements per feature buf
    const int TB = 256;
    const int gN   = (N + TB - 1) / TB;
    const int gE   = (E + TB - 1) / TB;
    const int gNF4 = (int)((NF4 + TB - 1) / TB);
    const int gSc  = (int)(((long long)E * 16 + TB - 1) / TB);
    const int gGem = (N + 3) / 4;

    // one-time prep (per call; deterministic)
    k_detect<<<1, 1>>>((const int*)eidx);
    k_prep<<<gE, TB>>>(eidx, srcI, dstI, E);
    k_deg_init<<<gN, TB>>>(dinv, N);
    k_deg_acc<<<gE, TB>>>(dstI, dinv, E);
    k_dinv<<<gN, TB>>>(dinv, N);
    k_norm<<<gE, TB>>>(srcI, dstI, dinv, nrm, E);

    // ---- layer 1: h = relu(norm_agg(x@W1) + b1)
    k_gemm<128, 0><<<gGem, TB>>>(x, W1, nullptr, bufA, N);
    k_zero4<<<gNF4, TB>>>((float4*)bufB, NF4);
    k_scatter<<<gSc, TB>>>(srcI, dstI, nrm, bufA, bufB, E);
    k_finalize<1><<<gNF4, TB>>>((const float4*)bufB, (const float4*)bufA, dinv,
                                (const float4*)b1, (float4*)bufC, N);

    // ---- layer 2: z = norm_agg(h@W2) + b2
    k_gemm<64, 0><<<gGem, TB>>>(bufC, W2, nullptr, bufA, N);
    k_zero4<<<gNF4, TB>>>((float4*)bufB, NF4);
    k_scatter<<<gSc, TB>>>(srcI, dstI, nrm, bufA, bufB, E);
    k_finalize<0><<<gNF4, TB>>>((const float4*)bufB, (const float4*)bufA, dinv,
                                (const float4*)b2, (float4*)zout, N);

    // ---- head: p = relu(z@Wp1 + bp1) @ Wp2 + bp2
    k_gemm<64, 2><<<gGem, TB>>>(zout, Wp1, bp1, bufC, N);
    k_gemm<64, 1><<<gGem, TB>>>(bufC, Wp2, bp2, pout, N);
}